// round 3
// baseline (speedup 1.0000x reference)
#include <cuda_runtime.h>
#include <math.h>

#define NN 10000
#define NE 160000
#define NG 64
#define EMB 128
#define MD 32
#define HID 642
#define EIN 321
#define PLD 644
#define CAT 768
#define EPSF 1e-5f

// ---------------- scratch (static device memory; no allocations) ----------------
__device__ float g_cat[NN * CAT];     // concat feats: block k = feats after layer k-1 (block 0 = embedding)
__device__ float g_hcat[NN * CAT];    // silu(g_cat)
__device__ float g_Pa[NN * PLD];      // feats @ W1[0:128]   (dst part), padded stride 644
__device__ float g_Pb[NN * PLD];      // feats @ W1[128:256] (src part)
__device__ float g_seg[NN * MD];      // per-node segment sum of edge messages
__device__ float g_cnt[NN];           // in-degree (by dst)
__device__ float g_z[NN * 160];       // [LN(feats) | m_i]
__device__ float g_h1[NN * 256];
__device__ float g_h2[NN * 128];
__device__ float g_f1[NN * 256];
__device__ float g_f2[NN * 256];
__device__ float g_f3[NN * 256];
__device__ float g_pool[NG * 256];
__device__ float g_pcnt[NG];

__device__ __forceinline__ float silu_f(float x) { return x / (1.f + __expf(-x)); }

// ---------------- small kernels ----------------
__global__ void k_zero_start() {
    int i = blockIdx.x * 256 + threadIdx.x;
    if (i < NN) g_cnt[i] = 0.f;
    if (i < NG * 256) g_pool[i] = 0.f;
    if (i < NG) g_pcnt[i] = 0.f;
}
__global__ void k_zero_seg() {
    int i = blockIdx.x * 256 + threadIdx.x;
    if (i < NN * MD) g_seg[i] = 0.f;
}
__global__ void k_deg(const int* __restrict__ eidx) {
    int e = blockIdx.x * 256 + threadIdx.x;
    if (e < NE) atomicAdd(&g_cnt[eidx[NE + e]], 1.f);
}
__global__ void k_embed(const int* __restrict__ atomids, const float* __restrict__ emb_w) {
    int i = blockIdx.x * 256 + threadIdx.x;
    if (i < NN * EMB) {
        int n = i >> 7, c = i & 127;
        g_cat[n * CAT + c] = emb_w[atomids[n] * EMB + c];
    }
}
__global__ void k_silucat() {
    int i = blockIdx.x * 256 + threadIdx.x;
    if (i < NN * CAT) g_hcat[i] = silu_f(g_cat[i]);
}
__global__ void k_pool(const int* __restrict__ batch) {
    int i = blockIdx.x * 256 + threadIdx.x;
    if (i < NN * 256) {
        int n = i >> 8, c = i & 255;
        atomicAdd(&g_pool[batch[n] * 256 + c], g_f3[i]);
    }
    if (i < NN) atomicAdd(&g_pcnt[batch[i]], 1.f);
}

// ---------------- generic tiled SGEMM: C[M,N] = act(A[M,K] @ B[K,N] + bias) ----------------
// block tile 64x64, K tile 8, 256 threads, 4x4 per thread
__global__ void k_sgemm(const float* __restrict__ A, const float* __restrict__ B,
                        const float* __restrict__ bias, float* __restrict__ C,
                        int M, int N, int K, int lda, int ldb, int ldc, int act) {
    __shared__ float As[8][65];
    __shared__ float Bs[8][64];
    int tid = threadIdx.x;
    int tx = tid & 15, ty = tid >> 4;
    int bm = blockIdx.y << 6, bn = blockIdx.x << 6;
    float acc[4][4];
#pragma unroll
    for (int i = 0; i < 4; i++)
#pragma unroll
        for (int j = 0; j < 4; j++) acc[i][j] = 0.f;

    for (int k0 = 0; k0 < K; k0 += 8) {
        for (int idx = tid; idx < 512; idx += 256) {
            int r = idx >> 3, c = idx & 7;
            int gr = bm + r, gc = k0 + c;
            As[c][r] = (gr < M && gc < K) ? A[gr * lda + gc] : 0.f;
        }
        for (int idx = tid; idx < 512; idx += 256) {
            int r = idx >> 6, c = idx & 63;
            int gr = k0 + r, gc = bn + c;
            Bs[r][c] = (gr < K && gc < N) ? B[gr * ldb + gc] : 0.f;
        }
        __syncthreads();
#pragma unroll
        for (int kk = 0; kk < 8; kk++) {
            float a0 = As[kk][ty * 4 + 0], a1 = As[kk][ty * 4 + 1];
            float a2 = As[kk][ty * 4 + 2], a3 = As[kk][ty * 4 + 3];
            float b0 = Bs[kk][tx * 4 + 0], b1v = Bs[kk][tx * 4 + 1];
            float b2v = Bs[kk][tx * 4 + 2], b3 = Bs[kk][tx * 4 + 3];
            acc[0][0] += a0 * b0; acc[0][1] += a0 * b1v; acc[0][2] += a0 * b2v; acc[0][3] += a0 * b3;
            acc[1][0] += a1 * b0; acc[1][1] += a1 * b1v; acc[1][2] += a1 * b2v; acc[1][3] += a1 * b3;
            acc[2][0] += a2 * b0; acc[2][1] += a2 * b1v; acc[2][2] += a2 * b2v; acc[2][3] += a2 * b3;
            acc[3][0] += a3 * b0; acc[3][1] += a3 * b1v; acc[3][2] += a3 * b2v; acc[3][3] += a3 * b3;
        }
        __syncthreads();
    }
#pragma unroll
    for (int i = 0; i < 4; i++) {
        int r = bm + ty * 4 + i;
        if (r >= M) continue;
#pragma unroll
        for (int j = 0; j < 4; j++) {
            int c = bn + tx * 4 + j;
            if (c >= N) continue;
            float v = acc[i][j] + (bias ? bias[c] : 0.f);
            if (act) v = silu_f(v);
            C[r * ldc + c] = v;
        }
    }
}

// ---------------- fused edge kernel ----------------
// hidden(642) = Pa[dst] + Pb[src] + fe(65) @ W1c + b1 ; H = silu(hidden)
// m(32) = silu(H @ W2 + b2) ; m = LN(m) ; atomic segment-sum into g_seg[dst]
__global__ void k_edge(const int* __restrict__ eidx, const float* __restrict__ coords,
                       const float* __restrict__ W1, const float* __restrict__ b1,
                       const float* __restrict__ W2, const float* __restrict__ b2,
                       const float* __restrict__ eng, const float* __restrict__ enb) {
    extern __shared__ float sm[];
    float* s_fe = sm;                   // 64*66 (per-edge fourier: [0:32)=sin [32:64)=cos [64]=d2)
    float* s_Hs = sm + 64 * 66;         // 64*66 hidden chunk (silu'd)
    float* s_W1c = sm + 2 * 64 * 66;    // 65*68 W1 fourier-rows chunk
    float* s_W2 = s_W1c + 65 * 68;      // 64*36 W2 chunk
    float* s_b1 = s_W2 + 64 * 36;       // 64
    int* s_src = (int*)(s_b1 + 64);     // 64
    int* s_dst = s_src + 64;            // 64

    int tid = threadIdx.x;
    int e0 = blockIdx.x << 6;

    if (tid < 64) {
        int e = e0 + tid;
        int s = eidx[e], d = eidx[NE + e];
        s_src[tid] = s; s_dst[tid] = d;
        float dx = coords[3 * s + 0] - coords[3 * d + 0];
        float dy = coords[3 * s + 1] - coords[3 * d + 1];
        float dz = coords[3 * s + 2] - coords[3 * d + 2];
        s_fe[tid * 66 + 64] = dx * dx + dy * dy + dz * dz;
    }
    __syncthreads();
    for (int idx = tid; idx < 64 * 32; idx += 256) {
        int e = idx >> 5, i = idx & 31;
        float d2 = s_fe[e * 66 + 64];
        float xs = d2 * __int_as_float((127 - i) << 23);  // * 2^-i
        float sv, cv;
        sincosf(xs, &sv, &cv);
        s_fe[e * 66 + i] = sv;
        s_fe[e * 66 + 32 + i] = cv;
    }

    int tx = tid & 15, ty = tid >> 4;
    int e2 = tid >> 2, nq = tid & 3;
    float mreg[8];
#pragma unroll
    for (int u = 0; u < 8; u++) mreg[u] = 0.f;

    for (int c = 0; c < 11; c++) {
        int cb = c << 6;
        __syncthreads();  // protect smem from previous iteration's readers (also orders fe writes)
        for (int idx = tid; idx < 65 * 64; idx += 256) {
            int i = idx >> 6, j = idx & 63;
            int gj = cb + j;
            s_W1c[i * 68 + j] = (gj < HID) ? W1[(256 + i) * HID + gj] : 0.f;
        }
        if (tid < 64) {
            int gj = cb + tid;
            s_b1[tid] = (gj < HID) ? b1[gj] : 0.f;
        }
        for (int idx = tid; idx < 64 * 32; idx += 256) {
            int j = idx >> 5, n = idx & 31;
            int gj = cb + j;
            s_W2[j * 36 + n] = (gj < HID) ? W2[gj * MD + n] : 0.f;
        }
        __syncthreads();

        // GEMM1: acc = Pa[dst] + Pb[src] + b1 + fe @ W1c
        float acc[4][4];
        int col0 = cb + (tx << 2);
#pragma unroll
        for (int ii = 0; ii < 4; ii++) {
            int e = (ty << 2) + ii;
            if (col0 < HID) {
                float4 pa = *(const float4*)&g_Pa[s_dst[e] * PLD + col0];
                float4 pb = *(const float4*)&g_Pb[s_src[e] * PLD + col0];
                acc[ii][0] = pa.x + pb.x + s_b1[(tx << 2) + 0];
                acc[ii][1] = pa.y + pb.y + s_b1[(tx << 2) + 1];
                acc[ii][2] = pa.z + pb.z + s_b1[(tx << 2) + 2];
                acc[ii][3] = pa.w + pb.w + s_b1[(tx << 2) + 3];
            } else {
                acc[ii][0] = acc[ii][1] = acc[ii][2] = acc[ii][3] = 0.f;
            }
        }
        for (int i = 0; i < 65; i++) {
            float4 w = *(const float4*)&s_W1c[i * 68 + (tx << 2)];
#pragma unroll
            for (int ii = 0; ii < 4; ii++) {
                float f = s_fe[((ty << 2) + ii) * 66 + i];
                acc[ii][0] += f * w.x;
                acc[ii][1] += f * w.y;
                acc[ii][2] += f * w.z;
                acc[ii][3] += f * w.w;
            }
        }
#pragma unroll
        for (int ii = 0; ii < 4; ii++) {
            int e = (ty << 2) + ii;
#pragma unroll
            for (int u = 0; u < 4; u++) {
                int gj = col0 + u;
                s_Hs[e * 66 + (tx << 2) + u] = (gj < HID) ? silu_f(acc[ii][u]) : 0.f;
            }
        }
        __syncthreads();

        // GEMM2: mreg += Hs_chunk @ W2_chunk   (thread owns edge e2, cols nq*8..nq*8+7)
        for (int j = 0; j < 64; j++) {
            float h = s_Hs[e2 * 66 + j];
            float4 w0 = *(const float4*)&s_W2[j * 36 + (nq << 3)];
            float4 w1 = *(const float4*)&s_W2[j * 36 + (nq << 3) + 4];
            mreg[0] += h * w0.x; mreg[1] += h * w0.y; mreg[2] += h * w0.z; mreg[3] += h * w0.w;
            mreg[4] += h * w1.x; mreg[5] += h * w1.y; mreg[6] += h * w1.z; mreg[7] += h * w1.w;
        }
    }

    // epilogue: bias + silu + LN(32) across the 4-lane quad, then atomic segment sum
    float vals[8];
    float S = 0.f;
#pragma unroll
    for (int u = 0; u < 8; u++) {
        float v = silu_f(mreg[u] + b2[(nq << 3) + u]);
        vals[u] = v;
        S += v;
    }
    S += __shfl_xor_sync(0xffffffffu, S, 1);
    S += __shfl_xor_sync(0xffffffffu, S, 2);
    float mean = S * (1.f / 32.f);
    float V = 0.f;
#pragma unroll
    for (int u = 0; u < 8; u++) {
        float d = vals[u] - mean;
        V += d * d;
    }
    V += __shfl_xor_sync(0xffffffffu, V, 1);
    V += __shfl_xor_sync(0xffffffffu, V, 2);
    V *= (1.f / 32.f);
    float inv = rsqrtf(V + EPSF);
    int dn = s_dst[e2];
#pragma unroll
    for (int u = 0; u < 8; u++) {
        int n = (nq << 3) + u;
        atomicAdd(&g_seg[dn * MD + n], (vals[u] - mean) * inv * eng[n] + enb[n]);
    }
}

// ---------------- node pre: m_i = LN(seg/cnt), z = [LN(feats) | m_i] ----------------
__global__ void k_node_pre(int off, const float* __restrict__ eng, const float* __restrict__ enb,
                           const float* __restrict__ n1g, const float* __restrict__ n1b) {
    int node = blockIdx.x * 8 + (threadIdx.x >> 5);
    int lane = threadIdx.x & 31;
    if (node >= NN) return;

    // m_i (32 dims, one per lane)
    float x = g_seg[node * MD + lane] / fmaxf(g_cnt[node], 1.f);
    float S = x;
#pragma unroll
    for (int o = 16; o; o >>= 1) S += __shfl_xor_sync(0xffffffffu, S, o);
    float mean = S * (1.f / 32.f);
    float d = x - mean;
    float V = d * d;
#pragma unroll
    for (int o = 16; o; o >>= 1) V += __shfl_xor_sync(0xffffffffu, V, o);
    V *= (1.f / 32.f);
    g_z[node * 160 + 128 + lane] = d * rsqrtf(V + EPSF) * eng[lane] + enb[lane];

    // LN(feats) (128 dims, 4 per lane)
    float4 v = *(const float4*)&g_cat[node * CAT + off + lane * 4];
    S = v.x + v.y + v.z + v.w;
#pragma unroll
    for (int o = 16; o; o >>= 1) S += __shfl_xor_sync(0xffffffffu, S, o);
    mean = S * (1.f / 128.f);
    float dx = v.x - mean, dy = v.y - mean, dz = v.z - mean, dw = v.w - mean;
    V = dx * dx + dy * dy + dz * dz + dw * dw;
#pragma unroll
    for (int o = 16; o; o >>= 1) V += __shfl_xor_sync(0xffffffffu, V, o);
    V *= (1.f / 128.f);
    float inv = rsqrtf(V + EPSF);
    float4 g4 = *(const float4*)&n1g[lane * 4];
    float4 b4 = *(const float4*)&n1b[lane * 4];
    float4 o4;
    o4.x = dx * inv * g4.x + b4.x;
    o4.y = dy * inv * g4.y + b4.y;
    o4.z = dz * inv * g4.z + b4.z;
    o4.w = dw * inv * g4.w + b4.w;
    *(float4*)&g_z[node * 160 + lane * 4] = o4;
}

// ---------------- node post: feats_new = feats_old + LN(h2) ----------------
__global__ void k_node_post(int off, const float* __restrict__ n2g, const float* __restrict__ n2b) {
    int node = blockIdx.x * 8 + (threadIdx.x >> 5);
    int lane = threadIdx.x & 31;
    if (node >= NN) return;
    float4 v = *(const float4*)&g_h2[node * 128 + lane * 4];
    float S = v.x + v.y + v.z + v.w;
#pragma unroll
    for (int o = 16; o; o >>= 1) S += __shfl_xor_sync(0xffffffffu, S, o);
    float mean = S * (1.f / 128.f);
    float dx = v.x - mean, dy = v.y - mean, dz = v.z - mean, dw = v.w - mean;
    float V = dx * dx + dy * dy + dz * dz + dw * dw;
#pragma unroll
    for (int o = 16; o; o >>= 1) V += __shfl_xor_sync(0xffffffffu, V, o);
    V *= (1.f / 128.f);
    float inv = rsqrtf(V + EPSF);
    float4 g4 = *(const float4*)&n2g[lane * 4];
    float4 b4 = *(const float4*)&n2b[lane * 4];
    float4 old = *(const float4*)&g_cat[node * CAT + off + lane * 4];
    float4 o4;
    o4.x = old.x + dx * inv * g4.x + b4.x;
    o4.y = old.y + dy * inv * g4.y + b4.y;
    o4.z = old.z + dz * inv * g4.z + b4.z;
    o4.w = old.w + dw * inv * g4.w + b4.w;
    *(float4*)&g_cat[node * CAT + off + 128 + lane * 4] = o4;
}

// ---------------- graph head: pooled MLP, one block per graph ----------------
__global__ void k_graph(const float* __restrict__ g1W, const float* __restrict__ g1b,
                        const float* __restrict__ g2W, const float* __restrict__ g2b,
                        const float* __restrict__ g3W, const float* __restrict__ g3b,
                        float* __restrict__ out) {
    __shared__ float h[256], t[256];
    int g = blockIdx.x, tid = threadIdx.x;
    float c = fmaxf(g_pcnt[g], 1.f);
    h[tid] = g_pool[g * 256 + tid] / c;
    __syncthreads();
    float a = g1b[tid];
    for (int k = 0; k < 256; k++) a += h[k] * g1W[k * 256 + tid];
    t[tid] = silu_f(a);
    __syncthreads();
    h[tid] = t[tid];
    __syncthreads();
    a = g2b[tid];
    for (int k = 0; k < 256; k++) a += h[k] * g2W[k * 256 + tid];
    t[tid] = silu_f(a);
    __syncthreads();
    h[tid] = t[tid];
    __syncthreads();
    t[tid] = h[tid] * g3W[tid];
    __syncthreads();
    for (int s = 128; s; s >>= 1) {
        if (tid < s) t[tid] += t[tid + s];
        __syncthreads();
    }
    if (tid == 0) out[g] = t[0] + g3b[0];
}

// ---------------- launch ----------------
extern "C" void kernel_launch(void* const* d_in, const int* in_sizes, int n_in,
                              void* d_out, int out_size) {
    const int* atomids = (const int*)d_in[0];
    const float* coords = (const float*)d_in[1];
    const int* eidx = (const int*)d_in[2];
    const int* batch = (const int*)d_in[3];
    const float* emb_w = (const float*)d_in[4];
    const float* eW1 = (const float*)d_in[5];
    const float* eb1 = (const float*)d_in[6];
    const float* eW2 = (const float*)d_in[7];
    const float* eb2 = (const float*)d_in[8];
    const float* en_g = (const float*)d_in[9];
    const float* en_b = (const float*)d_in[10];
    const float* nn1_g = (const float*)d_in[11];
    const float* nn1_b = (const float*)d_in[12];
    const float* nW1 = (const float*)d_in[13];
    const float* nb1 = (const float*)d_in[14];
    const float* nW2 = (const float*)d_in[15];
    const float* nb2 = (const float*)d_in[16];
    const float* nn2_g = (const float*)d_in[17];
    const float* nn2_b = (const float*)d_in[18];
    const float* f1W = (const float*)d_in[19];
    const float* f1b = (const float*)d_in[20];
    const float* f2W = (const float*)d_in[21];
    const float* f2b = (const float*)d_in[22];
    const float* f3W = (const float*)d_in[23];
    const float* f3b = (const float*)d_in[24];
    const float* g1W = (const float*)d_in[25];
    const float* g1b = (const float*)d_in[26];
    const float* g2W = (const float*)d_in[27];
    const float* g2b = (const float*)d_in[28];
    const float* g3W = (const float*)d_in[29];
    const float* g3b = (const float*)d_in[30];
    float* out = (float*)d_out;

    // true smem footprint of k_edge: fe(64*66) + Hs(64*66) + W1c(65*68) + W2(64*36)
    //                                 + b1(64) + src(64 int) + dst(64 int)
    const int smem_edge = (2 * 64 * 66 + 65 * 68 + 64 * 36 + 64 + 128) * 4;  // 61456 B

    cudaFuncSetAttribute(k_edge, cudaFuncAttributeMaxDynamicSharedMemorySize, smem_edge);

    float *pcat, *phcat, *pPa, *pPb, *pz, *ph1, *ph2, *pf1, *pf2, *pf3;
    cudaGetSymbolAddress((void**)&pcat, g_cat);
    cudaGetSymbolAddress((void**)&phcat, g_hcat);
    cudaGetSymbolAddress((void**)&pPa, g_Pa);
    cudaGetSymbolAddress((void**)&pPb, g_Pb);
    cudaGetSymbolAddress((void**)&pz, g_z);
    cudaGetSymbolAddress((void**)&ph1, g_h1);
    cudaGetSymbolAddress((void**)&ph2, g_h2);
    cudaGetSymbolAddress((void**)&pf1, g_f1);
    cudaGetSymbolAddress((void**)&pf2, g_f2);
    cudaGetSymbolAddress((void**)&pf3, g_f3);

    k_zero_start<<<64, 256>>>();
    k_deg<<<(NE + 255) / 256, 256>>>(eidx);
    k_embed<<<(NN * EMB + 255) / 256, 256>>>(atomids, emb_w);

    for (int k = 0; k < 5; k++) {
        int off = 128 * k;
        dim3 gP(11, 157);
        k_sgemm<<<gP, 256>>>(pcat + off, eW1 + (size_t)k * EIN * HID, nullptr, pPa,
                             NN, HID, EMB, CAT, HID, PLD, 0);
        k_sgemm<<<gP, 256>>>(pcat + off, eW1 + (size_t)k * EIN * HID + (size_t)EMB * HID, nullptr, pPb,
                             NN, HID, EMB, CAT, HID, PLD, 0);
        k_zero_seg<<<(NN * MD + 255) / 256, 256>>>();
        k_edge<<<NE / 64, 256, smem_edge>>>(eidx, coords,
                                            eW1 + (size_t)k * EIN * HID, eb1 + k * HID,
                                            eW2 + (size_t)k * HID * MD, eb2 + k * MD,
                                            en_g + k * MD, en_b + k * MD);
        k_node_pre<<<NN / 8, 256>>>(off, en_g + k * MD, en_b + k * MD,
                                    nn1_g + k * EMB, nn1_b + k * EMB);
        k_sgemm<<<dim3(4, 157), 256>>>(pz, nW1 + (size_t)k * 160 * 256, nb1 + k * 256, ph1,
                                       NN, 256, 160, 160, 256, 256, 1);
        k_sgemm<<<dim3(2, 157), 256>>>(ph1, nW2 + (size_t)k * 256 * 128, nb2 + k * 128, ph2,
                                       NN, 128, 256, 256, 128, 128, 0);
        k_node_post<<<NN / 8, 256>>>(off, nn2_g + k * EMB, nn2_b + k * EMB);
    }

    k_silucat<<<(NN * CAT + 255) / 256, 256>>>();
    k_sgemm<<<dim3(4, 157), 256>>>(phcat, f1W, f1b, pf1, NN, 256, CAT, CAT, 256, 256, 1);
    k_sgemm<<<dim3(4, 157), 256>>>(pf1, f2W, f2b, pf2, NN, 256, 256, 256, 256, 256, 1);
    k_sgemm<<<dim3(4, 157), 256>>>(pf2, f3W, f3b, pf3, NN, 256, 256, 256, 256, 256, 1);
    k_pool<<<(NN * 256 + 255) / 256, 256>>>(batch);
    k_graph<<<NG, 256>>>(g1W, g1b, g2W, g2b, g3W, g3b, out);
}

// round 4
// speedup vs baseline: 1.3502x; 1.3502x over previous
#include <cuda_runtime.h>
#include <math.h>

#define NN 10000
#define NE 160000
#define NG 64
#define EMB 128
#define MD 32
#define HID 642
#define EIN 321
#define PLD 644
#define CAT 768
#define EPSF 1e-5f

// ---------------- scratch (static device memory; no allocations) ----------------
__device__ float g_cat[NN * CAT];
__device__ float g_hcat[NN * CAT];
__device__ float g_Pa[NN * PLD];
__device__ float g_Pb[NN * PLD];
__device__ float g_seg[NN * MD];
__device__ float g_cnt[NN];
__device__ float g_z[NN * 160];
__device__ float g_h1[NN * 256];
__device__ float g_h2[NN * 128];
__device__ float g_f1[NN * 256];
__device__ float g_f2[NN * 256];
__device__ float g_f3[NN * 256];
__device__ float g_pool[NG * 256];
__device__ float g_pcnt[NG];

__device__ __forceinline__ float silu_f(float x) { return x / (1.f + __expf(-x)); }

__device__ __forceinline__ float to_tf32(float x) {
    unsigned u;
    asm("cvt.rna.tf32.f32 %0, %1;" : "=r"(u) : "f"(x));
    return __uint_as_float(u);
}

__device__ __forceinline__ void mma_tf32(float* c, unsigned a0, unsigned a1, unsigned a2, unsigned a3,
                                         unsigned b0, unsigned b1) {
    asm volatile(
        "mma.sync.aligned.m16n8k8.row.col.f32.tf32.tf32.f32 "
        "{%0,%1,%2,%3},{%4,%5,%6,%7},{%8,%9},{%0,%1,%2,%3};"
        : "+f"(c[0]), "+f"(c[1]), "+f"(c[2]), "+f"(c[3])
        : "r"(a0), "r"(a1), "r"(a2), "r"(a3), "r"(b0), "r"(b1));
}

// ---------------- small kernels ----------------
__global__ void k_zero_start() {
    int i = blockIdx.x * 256 + threadIdx.x;
    if (i < NN) g_cnt[i] = 0.f;
    if (i < NG * 256) g_pool[i] = 0.f;
    if (i < NG) g_pcnt[i] = 0.f;
}
__global__ void k_zero_seg() {
    int i = blockIdx.x * 256 + threadIdx.x;
    if (i < NN * MD) g_seg[i] = 0.f;
}
__global__ void k_deg(const int* __restrict__ eidx) {
    int e = blockIdx.x * 256 + threadIdx.x;
    if (e < NE) atomicAdd(&g_cnt[eidx[NE + e]], 1.f);
}
__global__ void k_embed(const int* __restrict__ atomids, const float* __restrict__ emb_w) {
    int i = blockIdx.x * 256 + threadIdx.x;
    if (i < NN * EMB) {
        int n = i >> 7, c = i & 127;
        g_cat[n * CAT + c] = emb_w[atomids[n] * EMB + c];
    }
}
__global__ void k_silucat() {
    int i = blockIdx.x * 256 + threadIdx.x;
    if (i < NN * CAT) g_hcat[i] = silu_f(g_cat[i]);
}
__global__ void k_pool(const int* __restrict__ batch) {
    int i = blockIdx.x * 256 + threadIdx.x;
    if (i < NN * 256) {
        int n = i >> 8, c = i & 255;
        atomicAdd(&g_pool[batch[n] * 256 + c], g_f3[i]);
    }
    if (i < NN) atomicAdd(&g_pcnt[batch[i]], 1.f);
}

// ---------------- generic tiled SGEMM (fp32, unchanged) ----------------
__global__ void k_sgemm(const float* __restrict__ A, const float* __restrict__ B,
                        const float* __restrict__ bias, float* __restrict__ C,
                        int M, int N, int K, int lda, int ldb, int ldc, int act) {
    __shared__ float As[8][65];
    __shared__ float Bs[8][64];
    int tid = threadIdx.x;
    int tx = tid & 15, ty = tid >> 4;
    int bm = blockIdx.y << 6, bn = blockIdx.x << 6;
    float acc[4][4];
#pragma unroll
    for (int i = 0; i < 4; i++)
#pragma unroll
        for (int j = 0; j < 4; j++) acc[i][j] = 0.f;

    for (int k0 = 0; k0 < K; k0 += 8) {
        for (int idx = tid; idx < 512; idx += 256) {
            int r = idx >> 3, c = idx & 7;
            int gr = bm + r, gc = k0 + c;
            As[c][r] = (gr < M && gc < K) ? A[gr * lda + gc] : 0.f;
        }
        for (int idx = tid; idx < 512; idx += 256) {
            int r = idx >> 6, c = idx & 63;
            int gr = k0 + r, gc = bn + c;
            Bs[r][c] = (gr < K && gc < N) ? B[gr * ldb + gc] : 0.f;
        }
        __syncthreads();
#pragma unroll
        for (int kk = 0; kk < 8; kk++) {
            float a0 = As[kk][ty * 4 + 0], a1 = As[kk][ty * 4 + 1];
            float a2 = As[kk][ty * 4 + 2], a3 = As[kk][ty * 4 + 3];
            float b0 = Bs[kk][tx * 4 + 0], b1v = Bs[kk][tx * 4 + 1];
            float b2v = Bs[kk][tx * 4 + 2], b3 = Bs[kk][tx * 4 + 3];
            acc[0][0] += a0 * b0; acc[0][1] += a0 * b1v; acc[0][2] += a0 * b2v; acc[0][3] += a0 * b3;
            acc[1][0] += a1 * b0; acc[1][1] += a1 * b1v; acc[1][2] += a1 * b2v; acc[1][3] += a1 * b3;
            acc[2][0] += a2 * b0; acc[2][1] += a2 * b1v; acc[2][2] += a2 * b2v; acc[2][3] += a2 * b3;
            acc[3][0] += a3 * b0; acc[3][1] += a3 * b1v; acc[3][2] += a3 * b2v; acc[3][3] += a3 * b3;
        }
        __syncthreads();
    }
#pragma unroll
    for (int i = 0; i < 4; i++) {
        int r = bm + ty * 4 + i;
        if (r >= M) continue;
#pragma unroll
        for (int j = 0; j < 4; j++) {
            int c = bn + tx * 4 + j;
            if (c >= N) continue;
            float v = acc[i][j] + (bias ? bias[c] : 0.f);
            if (act) v = silu_f(v);
            C[r * ldc + c] = v;
        }
    }
}

// ---------------- fused edge kernel, tf32 tensor cores ----------------
// 128 edges/block, 256 threads (8 warps, each owns 16 edge-rows).
// Per 64-col chunk: C1 = FE(tf32)[128x72] @ W1c(tf32)[72x64] (mma)
//   H = tf32(silu(C1 + Pa[dst]+Pb[src]+b1))   (PQ staged fp32 in smem)
//   Macc += H[128x64] @ W2c(tf32)[64x32]      (mma, persistent accum)
// Epilogue: silu(+b2), LN32 via quad shuffles, atomic segment-sum.
__global__ __launch_bounds__(256) void k_edge2(
    const int* __restrict__ eidx, const float* __restrict__ coords,
    const float* __restrict__ W1, const float* __restrict__ b1,
    const float* __restrict__ W2, const float* __restrict__ b2,
    const float* __restrict__ eng, const float* __restrict__ enb) {
    extern __shared__ float sm[];
    float* s_fe = sm;                       // 128 x 76  (tf32 bits; cols 0..64 data, 65..71 zero)
    float* s_H = sm + 128 * 76;             // 128 x 68  (PQ fp32, then H tf32)
    float* s_W1c = s_H + 128 * 68;          // 72 x 68
    float* s_W2c = s_W1c + 72 * 68;         // 64 x 36
    float* s_d2 = s_W2c + 64 * 36;          // 128
    int* s_src = (int*)(s_d2 + 128);        // 128
    int* s_dst = s_src + 128;               // 128

    int tid = threadIdx.x;
    int e0 = blockIdx.x << 7;

    if (tid < 128) {
        int e = e0 + tid;
        int s = eidx[e], d = eidx[NE + e];
        s_src[tid] = s; s_dst[tid] = d;
        float dx = coords[3 * s + 0] - coords[3 * d + 0];
        float dy = coords[3 * s + 1] - coords[3 * d + 1];
        float dz = coords[3 * s + 2] - coords[3 * d + 2];
        float d2 = dx * dx + dy * dy + dz * dz;
        s_d2[tid] = d2;
        s_fe[tid * 76 + 64] = to_tf32(d2);
#pragma unroll
        for (int j = 65; j < 72; j++) s_fe[tid * 76 + j] = 0.f;
    }
    __syncthreads();
    for (int idx = tid; idx < 128 * 32; idx += 256) {
        int e = idx >> 5, i = idx & 31;
        float xs = s_d2[e] * __int_as_float((127 - i) << 23);
        float sv, cv;
        sincosf(xs, &sv, &cv);
        s_fe[e * 76 + i] = to_tf32(sv);
        s_fe[e * 76 + 32 + i] = to_tf32(cv);
    }

    int wid = tid >> 5, lane = tid & 31;
    int g = lane >> 2, tig = lane & 3;
    int r0 = wid << 4;

    float acc[4][4];
#pragma unroll
    for (int t = 0; t < 4; t++)
#pragma unroll
        for (int u = 0; u < 4; u++) acc[t][u] = 0.f;

    for (int c = 0; c < 11; c++) {
        int cb = c << 6;
        __syncthreads();
        // W1c chunk (fourier rows 256..320 of W1), tf32, zero padded
        for (int idx = tid; idx < 72 * 64; idx += 256) {
            int k = idx >> 6, n = idx & 63;
            int gj = cb + n;
            float v = (k < 65 && gj < HID) ? W1[(256 + k) * HID + gj] : 0.f;
            s_W1c[k * 68 + n] = to_tf32(v);
        }
        // W2 chunk, tf32
        for (int idx = tid; idx < 64 * 32; idx += 256) {
            int j = idx >> 5, n = idx & 31;
            int gj = cb + j;
            float v = (gj < HID) ? W2[gj * MD + n] : 0.f;
            s_W2c[j * 36 + n] = to_tf32(v);
        }
        // PQ = Pa[dst]+Pb[src]+b1 (exact fp32) into s_H
        for (int it = tid; it < 128 * 16; it += 256) {
            int e = it >> 4, q = it & 15;
            int col = cb + (q << 2);
            float4 r = make_float4(0.f, 0.f, 0.f, 0.f);
            if (col < HID) {
                float4 pa = *(const float4*)&g_Pa[s_dst[e] * PLD + col];
                float4 pb = *(const float4*)&g_Pb[s_src[e] * PLD + col];
                r.x = pa.x + pb.x + b1[col];
                r.y = (col + 1 < HID) ? pa.y + pb.y + b1[col + 1] : 0.f;
                r.z = (col + 2 < HID) ? pa.z + pb.z + b1[col + 2] : 0.f;
                r.w = (col + 3 < HID) ? pa.w + pb.w + b1[col + 3] : 0.f;
            }
            *(float4*)&s_H[e * 68 + (q << 2)] = r;
        }
        __syncthreads();

        // GEMM1: c1 = FE @ W1c   (warp: rows r0..r0+15, cols 0..63)
        float c1[8][4];
#pragma unroll
        for (int t = 0; t < 8; t++)
#pragma unroll
            for (int u = 0; u < 4; u++) c1[t][u] = 0.f;
#pragma unroll
        for (int ks = 0; ks < 9; ks++) {
            int k0 = ks << 3;
            unsigned a0 = __float_as_uint(s_fe[(r0 + g) * 76 + k0 + tig]);
            unsigned a1 = __float_as_uint(s_fe[(r0 + g + 8) * 76 + k0 + tig]);
            unsigned a2 = __float_as_uint(s_fe[(r0 + g) * 76 + k0 + tig + 4]);
            unsigned a3 = __float_as_uint(s_fe[(r0 + g + 8) * 76 + k0 + tig + 4]);
#pragma unroll
            for (int t = 0; t < 8; t++) {
                unsigned b0v = __float_as_uint(s_W1c[(k0 + tig) * 68 + (t << 3) + g]);
                unsigned b1v = __float_as_uint(s_W1c[(k0 + tig + 4) * 68 + (t << 3) + g]);
                mma_tf32(c1[t], a0, a1, a2, a3, b0v, b1v);
            }
        }
        // epilogue: H = tf32(silu(c1 + PQ)), in place (each element owned by one thread)
#pragma unroll
        for (int t = 0; t < 8; t++) {
            int col = (t << 3) + (tig << 1);
            int i00 = (r0 + g) * 68 + col;
            int i10 = (r0 + g + 8) * 68 + col;
            s_H[i00] = to_tf32(silu_f(c1[t][0] + s_H[i00]));
            s_H[i00 + 1] = to_tf32(silu_f(c1[t][1] + s_H[i00 + 1]));
            s_H[i10] = to_tf32(silu_f(c1[t][2] + s_H[i10]));
            s_H[i10 + 1] = to_tf32(silu_f(c1[t][3] + s_H[i10 + 1]));
        }
        __syncthreads();

        // GEMM2: acc += H @ W2c  (warp: rows r0..r0+15, cols 0..31)
#pragma unroll
        for (int ks = 0; ks < 8; ks++) {
            int k0 = ks << 3;
            unsigned a0 = __float_as_uint(s_H[(r0 + g) * 68 + k0 + tig]);
            unsigned a1 = __float_as_uint(s_H[(r0 + g + 8) * 68 + k0 + tig]);
            unsigned a2 = __float_as_uint(s_H[(r0 + g) * 68 + k0 + tig + 4]);
            unsigned a3 = __float_as_uint(s_H[(r0 + g + 8) * 68 + k0 + tig + 4]);
#pragma unroll
            for (int t = 0; t < 4; t++) {
                unsigned b0v = __float_as_uint(s_W2c[(k0 + tig) * 36 + (t << 3) + g]);
                unsigned b1v = __float_as_uint(s_W2c[(k0 + tig + 4) * 36 + (t << 3) + g]);
                mma_tf32(acc[t], a0, a1, a2, a3, b0v, b1v);
            }
        }
    }

    // message epilogue: silu(+b2), LN over 32 cols (held by the 4 lanes of each quad)
    float vlo[8], vhi[8];
    float Slo = 0.f, Shi = 0.f;
#pragma unroll
    for (int t = 0; t < 4; t++) {
        int col = (t << 3) + (tig << 1);
        float v0 = silu_f(acc[t][0] + b2[col]);
        float v1 = silu_f(acc[t][1] + b2[col + 1]);
        float v2 = silu_f(acc[t][2] + b2[col]);
        float v3 = silu_f(acc[t][3] + b2[col + 1]);
        vlo[t * 2] = v0; vlo[t * 2 + 1] = v1;
        vhi[t * 2] = v2; vhi[t * 2 + 1] = v3;
        Slo += v0 + v1; Shi += v2 + v3;
    }
    Slo += __shfl_xor_sync(0xffffffffu, Slo, 1);
    Slo += __shfl_xor_sync(0xffffffffu, Slo, 2);
    Shi += __shfl_xor_sync(0xffffffffu, Shi, 1);
    Shi += __shfl_xor_sync(0xffffffffu, Shi, 2);
    float mlo = Slo * (1.f / 32.f), mhi = Shi * (1.f / 32.f);
    float Vlo = 0.f, Vhi = 0.f;
#pragma unroll
    for (int u = 0; u < 8; u++) {
        float d0 = vlo[u] - mlo; Vlo += d0 * d0;
        float d1 = vhi[u] - mhi; Vhi += d1 * d1;
    }
    Vlo += __shfl_xor_sync(0xffffffffu, Vlo, 1);
    Vlo += __shfl_xor_sync(0xffffffffu, Vlo, 2);
    Vhi += __shfl_xor_sync(0xffffffffu, Vhi, 1);
    Vhi += __shfl_xor_sync(0xffffffffu, Vhi, 2);
    float ilo = rsqrtf(Vlo * (1.f / 32.f) + EPSF);
    float ihi = rsqrtf(Vhi * (1.f / 32.f) + EPSF);
    int dlo = s_dst[r0 + g], dhi = s_dst[r0 + g + 8];
#pragma unroll
    for (int t = 0; t < 4; t++) {
#pragma unroll
        for (int d = 0; d < 2; d++) {
            int col = (t << 3) + (tig << 1) + d;
            atomicAdd(&g_seg[dlo * MD + col], (vlo[t * 2 + d] - mlo) * ilo * eng[col] + enb[col]);
            atomicAdd(&g_seg[dhi * MD + col], (vhi[t * 2 + d] - mhi) * ihi * eng[col] + enb[col]);
        }
    }
}

// ---------------- node pre: m_i = LN(seg/cnt), z = [LN(feats) | m_i] ----------------
__global__ void k_node_pre(int off, const float* __restrict__ eng, const float* __restrict__ enb,
                           const float* __restrict__ n1g, const float* __restrict__ n1b) {
    int node = blockIdx.x * 8 + (threadIdx.x >> 5);
    int lane = threadIdx.x & 31;
    if (node >= NN) return;

    float x = g_seg[node * MD + lane] / fmaxf(g_cnt[node], 1.f);
    float S = x;
#pragma unroll
    for (int o = 16; o; o >>= 1) S += __shfl_xor_sync(0xffffffffu, S, o);
    float mean = S * (1.f / 32.f);
    float d = x - mean;
    float V = d * d;
#pragma unroll
    for (int o = 16; o; o >>= 1) V += __shfl_xor_sync(0xffffffffu, V, o);
    V *= (1.f / 32.f);
    g_z[node * 160 + 128 + lane] = d * rsqrtf(V + EPSF) * eng[lane] + enb[lane];

    float4 v = *(const float4*)&g_cat[node * CAT + off + lane * 4];
    S = v.x + v.y + v.z + v.w;
#pragma unroll
    for (int o = 16; o; o >>= 1) S += __shfl_xor_sync(0xffffffffu, S, o);
    mean = S * (1.f / 128.f);
    float dx = v.x - mean, dy = v.y - mean, dz = v.z - mean, dw = v.w - mean;
    V = dx * dx + dy * dy + dz * dz + dw * dw;
#pragma unroll
    for (int o = 16; o; o >>= 1) V += __shfl_xor_sync(0xffffffffu, V, o);
    V *= (1.f / 128.f);
    float inv = rsqrtf(V + EPSF);
    float4 g4 = *(const float4*)&n1g[lane * 4];
    float4 b4 = *(const float4*)&n1b[lane * 4];
    float4 o4;
    o4.x = dx * inv * g4.x + b4.x;
    o4.y = dy * inv * g4.y + b4.y;
    o4.z = dz * inv * g4.z + b4.z;
    o4.w = dw * inv * g4.w + b4.w;
    *(float4*)&g_z[node * 160 + lane * 4] = o4;
}

// ---------------- node post: feats_new = feats_old + LN(h2) ----------------
__global__ void k_node_post(int off, const float* __restrict__ n2g, const float* __restrict__ n2b) {
    int node = blockIdx.x * 8 + (threadIdx.x >> 5);
    int lane = threadIdx.x & 31;
    if (node >= NN) return;
    float4 v = *(const float4*)&g_h2[node * 128 + lane * 4];
    float S = v.x + v.y + v.z + v.w;
#pragma unroll
    for (int o = 16; o; o >>= 1) S += __shfl_xor_sync(0xffffffffu, S, o);
    float mean = S * (1.f / 128.f);
    float dx = v.x - mean, dy = v.y - mean, dz = v.z - mean, dw = v.w - mean;
    float V = dx * dx + dy * dy + dz * dz + dw * dw;
#pragma unroll
    for (int o = 16; o; o >>= 1) V += __shfl_xor_sync(0xffffffffu, V, o);
    V *= (1.f / 128.f);
    float inv = rsqrtf(V + EPSF);
    float4 g4 = *(const float4*)&n2g[lane * 4];
    float4 b4 = *(const float4*)&n2b[lane * 4];
    float4 old = *(const float4*)&g_cat[node * CAT + off + lane * 4];
    float4 o4;
    o4.x = old.x + dx * inv * g4.x + b4.x;
    o4.y = old.y + dy * inv * g4.y + b4.y;
    o4.z = old.z + dz * inv * g4.z + b4.z;
    o4.w = old.w + dw * inv * g4.w + b4.w;
    *(float4*)&g_cat[node * CAT + off + 128 + lane * 4] = o4;
}

// ---------------- graph head ----------------
__global__ void k_graph(const float* __restrict__ g1W, const float* __restrict__ g1b,
                        const float* __restrict__ g2W, const float* __restrict__ g2b,
                        const float* __restrict__ g3W, const float* __restrict__ g3b,
                        float* __restrict__ out) {
    __shared__ float h[256], t[256];
    int g = blockIdx.x, tid = threadIdx.x;
    float c = fmaxf(g_pcnt[g], 1.f);
    h[tid] = g_pool[g * 256 + tid] / c;
    __syncthreads();
    float a = g1b[tid];
    for (int k = 0; k < 256; k++) a += h[k] * g1W[k * 256 + tid];
    t[tid] = silu_f(a);
    __syncthreads();
    h[tid] = t[tid];
    __syncthreads();
    a = g2b[tid];
    for (int k = 0; k < 256; k++) a += h[k] * g2W[k * 256 + tid];
    t[tid] = silu_f(a);
    __syncthreads();
    h[tid] = t[tid];
    __syncthreads();
    t[tid] = h[tid] * g3W[tid];
    __syncthreads();
    for (int s = 128; s; s >>= 1) {
        if (tid < s) t[tid] += t[tid + s];
        __syncthreads();
    }
    if (tid == 0) out[g] = t[0] + g3b[0];
}

// ---------------- launch ----------------
extern "C" void kernel_launch(void* const* d_in, const int* in_sizes, int n_in,
                              void* d_out, int out_size) {
    const int* atomids = (const int*)d_in[0];
    const float* coords = (const float*)d_in[1];
    const int* eidx = (const int*)d_in[2];
    const int* batch = (const int*)d_in[3];
    const float* emb_w = (const float*)d_in[4];
    const float* eW1 = (const float*)d_in[5];
    const float* eb1 = (const float*)d_in[6];
    const float* eW2 = (const float*)d_in[7];
    const float* eb2 = (const float*)d_in[8];
    const float* en_g = (const float*)d_in[9];
    const float* en_b = (const float*)d_in[10];
    const float* nn1_g = (const float*)d_in[11];
    const float* nn1_b = (const float*)d_in[12];
    const float* nW1 = (const float*)d_in[13];
    const float* nb1 = (const float*)d_in[14];
    const float* nW2 = (const float*)d_in[15];
    const float* nb2 = (const float*)d_in[16];
    const float* nn2_g = (const float*)d_in[17];
    const float* nn2_b = (const float*)d_in[18];
    const float* f1W = (const float*)d_in[19];
    const float* f1b = (const float*)d_in[20];
    const float* f2W = (const float*)d_in[21];
    const float* f2b = (const float*)d_in[22];
    const float* f3W = (const float*)d_in[23];
    const float* f3b = (const float*)d_in[24];
    const float* g1W = (const float*)d_in[25];
    const float* g1b = (const float*)d_in[26];
    const float* g2W = (const float*)d_in[27];
    const float* g2b = (const float*)d_in[28];
    const float* g3W = (const float*)d_in[29];
    const float* g3b = (const float*)d_in[30];
    float* out = (float*)d_out;

    // smem: fe(128*76) + H(128*68) + W1c(72*68) + W2c(64*36) + d2(128) + src/dst(256 ints)
    const int smem_edge = (128 * 76 + 128 * 68 + 72 * 68 + 64 * 36 + 128 + 256) * 4;  // 104064 B
    cudaFuncSetAttribute(k_edge2, cudaFuncAttributeMaxDynamicSharedMemorySize, smem_edge);

    float *pcat, *phcat, *pPa, *pPb, *pz, *ph1, *ph2, *pf1, *pf2, *pf3;
    cudaGetSymbolAddress((void**)&pcat, g_cat);
    cudaGetSymbolAddress((void**)&phcat, g_hcat);
    cudaGetSymbolAddress((void**)&pPa, g_Pa);
    cudaGetSymbolAddress((void**)&pPb, g_Pb);
    cudaGetSymbolAddress((void**)&pz, g_z);
    cudaGetSymbolAddress((void**)&ph1, g_h1);
    cudaGetSymbolAddress((void**)&ph2, g_h2);
    cudaGetSymbolAddress((void**)&pf1, g_f1);
    cudaGetSymbolAddress((void**)&pf2, g_f2);
    cudaGetSymbolAddress((void**)&pf3, g_f3);

    k_zero_start<<<64, 256>>>();
    k_deg<<<(NE + 255) / 256, 256>>>(eidx);
    k_embed<<<(NN * EMB + 255) / 256, 256>>>(atomids, emb_w);

    for (int k = 0; k < 5; k++) {
        int off = 128 * k;
        dim3 gP(11, 157);
        k_sgemm<<<gP, 256>>>(pcat + off, eW1 + (size_t)k * EIN * HID, nullptr, pPa,
                             NN, HID, EMB, CAT, HID, PLD, 0);
        k_sgemm<<<gP, 256>>>(pcat + off, eW1 + (size_t)k * EIN * HID + (size_t)EMB * HID, nullptr, pPb,
                             NN, HID, EMB, CAT, HID, PLD, 0);
        k_zero_seg<<<(NN * MD + 255) / 256, 256>>>();
        k_edge2<<<NE / 128, 256, smem_edge>>>(eidx, coords,
                                              eW1 + (size_t)k * EIN * HID, eb1 + k * HID,
                                              eW2 + (size_t)k * HID * MD, eb2 + k * MD,
                                              en_g + k * MD, en_b + k * MD);
        k_node_pre<<<NN / 8, 256>>>(off, en_g + k * MD, en_b + k * MD,
                                    nn1_g + k * EMB, nn1_b + k * EMB);
        k_sgemm<<<dim3(4, 157), 256>>>(pz, nW1 + (size_t)k * 160 * 256, nb1 + k * 256, ph1,
                                       NN, 256, 160, 160, 256, 256, 1);
        k_sgemm<<<dim3(2, 157), 256>>>(ph1, nW2 + (size_t)k * 256 * 128, nb2 + k * 128, ph2,
                                       NN, 128, 256, 256, 128, 128, 0);
        k_node_post<<<NN / 8, 256>>>(off, nn2_g + k * EMB, nn2_b + k * EMB);
    }

    k_silucat<<<(NN * CAT + 255) / 256, 256>>>();
    k_sgemm<<<dim3(4, 157), 256>>>(phcat, f1W, f1b, pf1, NN, 256, CAT, CAT, 256, 256, 1);
    k_sgemm<<<dim3(4, 157), 256>>>(pf1, f2W, f2b, pf2, NN, 256, 256, 256, 256, 256, 1);
    k_sgemm<<<dim3(4, 157), 256>>>(pf2, f3W, f3b, pf3, NN, 256, 256, 256, 256, 256, 1);
    k_pool<<<(NN * 256 + 255) / 256, 256>>>(batch);
    k_graph<<<NG, 256>>>(g1W, g1b, g2W, g2b, g3W, g3b, out);
}

// round 5
// speedup vs baseline: 1.6611x; 1.2302x over previous
#include <cuda_runtime.h>
#include <math.h>

#define NN 10000
#define NE 160000
#define NG 64
#define EMB 128
#define MD 32
#define HID 642
#define EIN 321
#define PLD 644
#define CAT 768
#define EPSF 1e-5f

// ---------------- scratch (static device memory; no allocations) ----------------
__device__ float g_cat[NN * CAT];
__device__ float g_hcat[NN * CAT];
__device__ float g_Pa[NN * PLD];
__device__ float g_Pb[NN * PLD];
__device__ float g_seg[NN * MD];
__device__ float g_cnt[NN];
__device__ float g_z[NN * 160];
__device__ float g_h1[NN * 256];
__device__ float g_h2[NN * 128];
__device__ float g_f1[NN * 256];
__device__ float g_f2[NN * 256];
__device__ float g_f3[NN * 256];
__device__ float g_pool[NG * 256];
__device__ float g_pcnt[NG];

// silu with fast reciprocal (MUFU.RCP, ~2ulp) — negligible vs tf32 noise
__device__ __forceinline__ float silu_f(float x) {
    return x * __fdividef(1.f, 1.f + __expf(-x));
}

__device__ __forceinline__ float to_tf32(float x) {
    unsigned u;
    asm("cvt.rna.tf32.f32 %0, %1;" : "=r"(u) : "f"(x));
    return __uint_as_float(u);
}

__device__ __forceinline__ void mma_tf32(float* c, unsigned a0, unsigned a1, unsigned a2, unsigned a3,
                                         unsigned b0, unsigned b1) {
    asm volatile(
        "mma.sync.aligned.m16n8k8.row.col.f32.tf32.tf32.f32 "
        "{%0,%1,%2,%3},{%4,%5,%6,%7},{%8,%9},{%0,%1,%2,%3};"
        : "+f"(c[0]), "+f"(c[1]), "+f"(c[2]), "+f"(c[3])
        : "r"(a0), "r"(a1), "r"(a2), "r"(a3), "r"(b0), "r"(b1));
}

// ---------------- small kernels ----------------
__global__ void k_zero_start() {
    int i = blockIdx.x * 256 + threadIdx.x;
    if (i < NN) g_cnt[i] = 0.f;
    if (i < NG * 256) g_pool[i] = 0.f;
    if (i < NG) g_pcnt[i] = 0.f;
}
__global__ void k_zero_seg() {
    int i = blockIdx.x * 256 + threadIdx.x;
    if (i < NN * MD) g_seg[i] = 0.f;
}
__global__ void k_deg(const int* __restrict__ eidx) {
    int e = blockIdx.x * 256 + threadIdx.x;
    if (e < NE) atomicAdd(&g_cnt[eidx[NE + e]], 1.f);
}
__global__ void k_embed(const int* __restrict__ atomids, const float* __restrict__ emb_w) {
    int i = blockIdx.x * 256 + threadIdx.x;
    if (i < NN * EMB) {
        int n = i >> 7, c = i & 127;
        g_cat[n * CAT + c] = emb_w[atomids[n] * EMB + c];
    }
}
__global__ void k_silucat() {
    int i = blockIdx.x * 256 + threadIdx.x;
    if (i < NN * CAT) g_hcat[i] = silu_f(g_cat[i]);
}
__global__ void k_pool(const int* __restrict__ batch) {
    int i = blockIdx.x * 256 + threadIdx.x;
    if (i < NN * 256) {
        int n = i >> 8, c = i & 255;
        atomicAdd(&g_pool[batch[n] * 256 + c], g_f3[i]);
    }
    if (i < NN) atomicAdd(&g_pcnt[batch[i]], 1.f);
}

// ---------------- 3xTF32 tensor-core GEMM: C = act(A@B + bias), near-fp32 ----------------
// Tile 128(M) x 64(N), K step 16. 8 warps; warp w owns rows w*16..w*16+15, all 64 cols.
// Split both operands hi/lo (tf32), 3 mma per step: hi*hi + hi*lo + lo*hi  (err ~2^-22).
// Requires: K % 16 == 0, N even, lda % 4 == 0, A base 16B-aligned, ldc even.
__global__ __launch_bounds__(256) void k_gemm3t(
    const float* __restrict__ A, const float* __restrict__ B,
    const float* __restrict__ bias, float* __restrict__ C,
    int M, int N, int K, int lda, int ldb, int ldc, int act) {
    __shared__ float sAh[128 * 20], sAl[128 * 20];
    __shared__ float sBh[16 * 68], sBl[16 * 68];
    int tid = threadIdx.x;
    int wid = tid >> 5, lane = tid & 31;
    int g = lane >> 2, tig = lane & 3;
    int r0 = wid << 4;
    int bm = blockIdx.y << 7, bn = blockIdx.x << 6;

    float acc[8][4];
#pragma unroll
    for (int t = 0; t < 8; t++)
#pragma unroll
        for (int u = 0; u < 4; u++) acc[t][u] = 0.f;

    for (int k0 = 0; k0 < K; k0 += 16) {
        __syncthreads();
        // stage A tile 128x16 (float4 loads), split hi/lo
        {
            int r = tid >> 1, c0 = (tid & 1) << 3;
            int gr = bm + r;
            float4 v0 = make_float4(0.f, 0.f, 0.f, 0.f), v1 = v0;
            if (gr < M) {
                const float* ap = A + (size_t)gr * lda + k0 + c0;
                v0 = *(const float4*)ap;
                v1 = *(const float4*)(ap + 4);
            }
            float* ph = &sAh[r * 20 + c0];
            float* pl = &sAl[r * 20 + c0];
            float h;
            h = to_tf32(v0.x); ph[0] = h; pl[0] = to_tf32(v0.x - h);
            h = to_tf32(v0.y); ph[1] = h; pl[1] = to_tf32(v0.y - h);
            h = to_tf32(v0.z); ph[2] = h; pl[2] = to_tf32(v0.z - h);
            h = to_tf32(v0.w); ph[3] = h; pl[3] = to_tf32(v0.w - h);
            h = to_tf32(v1.x); ph[4] = h; pl[4] = to_tf32(v1.x - h);
            h = to_tf32(v1.y); ph[5] = h; pl[5] = to_tf32(v1.y - h);
            h = to_tf32(v1.z); ph[6] = h; pl[6] = to_tf32(v1.z - h);
            h = to_tf32(v1.w); ph[7] = h; pl[7] = to_tf32(v1.w - h);
        }
        // stage B tile 16x64 (scalar, ldb may be odd), split hi/lo
        for (int idx = tid; idx < 16 * 64; idx += 256) {
            int kr = idx >> 6, nc = idx & 63;
            int gc = bn + nc;
            float v = (gc < N) ? B[(size_t)(k0 + kr) * ldb + gc] : 0.f;
            float hcv = to_tf32(v);
            sBh[kr * 68 + nc] = hcv;
            sBl[kr * 68 + nc] = to_tf32(v - hcv);
        }
        __syncthreads();
#pragma unroll
        for (int ks = 0; ks < 2; ks++) {
            int kk = ks << 3;
            unsigned ah0 = __float_as_uint(sAh[(r0 + g) * 20 + kk + tig]);
            unsigned ah1 = __float_as_uint(sAh[(r0 + g + 8) * 20 + kk + tig]);
            unsigned ah2 = __float_as_uint(sAh[(r0 + g) * 20 + kk + tig + 4]);
            unsigned ah3 = __float_as_uint(sAh[(r0 + g + 8) * 20 + kk + tig + 4]);
            unsigned al0 = __float_as_uint(sAl[(r0 + g) * 20 + kk + tig]);
            unsigned al1 = __float_as_uint(sAl[(r0 + g + 8) * 20 + kk + tig]);
            unsigned al2 = __float_as_uint(sAl[(r0 + g) * 20 + kk + tig + 4]);
            unsigned al3 = __float_as_uint(sAl[(r0 + g + 8) * 20 + kk + tig + 4]);
#pragma unroll
            for (int t = 0; t < 8; t++) {
                unsigned bh0 = __float_as_uint(sBh[(kk + tig) * 68 + (t << 3) + g]);
                unsigned bh1 = __float_as_uint(sBh[(kk + tig + 4) * 68 + (t << 3) + g]);
                unsigned bl0 = __float_as_uint(sBl[(kk + tig) * 68 + (t << 3) + g]);
                unsigned bl1 = __float_as_uint(sBl[(kk + tig + 4) * 68 + (t << 3) + g]);
                mma_tf32(acc[t], ah0, ah1, ah2, ah3, bh0, bh1);
                mma_tf32(acc[t], ah0, ah1, ah2, ah3, bl0, bl1);
                mma_tf32(acc[t], al0, al1, al2, al3, bh0, bh1);
            }
        }
    }

    // epilogue: bias + optional silu, float2 stores (N even -> pairs both valid/invalid)
    int row0 = bm + r0 + g, row1 = row0 + 8;
#pragma unroll
    for (int t = 0; t < 8; t++) {
        int col = bn + (t << 3) + (tig << 1);
        if (col >= N) continue;
        float b0v = bias ? bias[col] : 0.f;
        float b1v = bias ? bias[col + 1] : 0.f;
        float v00 = acc[t][0] + b0v, v01 = acc[t][1] + b1v;
        float v10 = acc[t][2] + b0v, v11 = acc[t][3] + b1v;
        if (act) { v00 = silu_f(v00); v01 = silu_f(v01); v10 = silu_f(v10); v11 = silu_f(v11); }
        if (row0 < M) *(float2*)&C[(size_t)row0 * ldc + col] = make_float2(v00, v01);
        if (row1 < M) *(float2*)&C[(size_t)row1 * ldc + col] = make_float2(v10, v11);
    }
}

// ---------------- fused edge kernel, tf32 tensor cores ----------------
__global__ __launch_bounds__(256) void k_edge2(
    const int* __restrict__ eidx, const float* __restrict__ coords,
    const float* __restrict__ W1, const float* __restrict__ b1,
    const float* __restrict__ W2, const float* __restrict__ b2,
    const float* __restrict__ eng, const float* __restrict__ enb) {
    extern __shared__ float sm[];
    float* s_fe = sm;                       // 128 x 76
    float* s_H = sm + 128 * 76;             // 128 x 68
    float* s_W1c = s_H + 128 * 68;          // 72 x 68
    float* s_W2c = s_W1c + 72 * 68;         // 64 x 36
    float* s_d2 = s_W2c + 64 * 36;          // 128
    int* s_src = (int*)(s_d2 + 128);        // 128
    int* s_dst = s_src + 128;               // 128

    int tid = threadIdx.x;
    int e0 = blockIdx.x << 7;

    if (tid < 128) {
        int e = e0 + tid;
        int s = eidx[e], d = eidx[NE + e];
        s_src[tid] = s; s_dst[tid] = d;
        float dx = coords[3 * s + 0] - coords[3 * d + 0];
        float dy = coords[3 * s + 1] - coords[3 * d + 1];
        float dz = coords[3 * s + 2] - coords[3 * d + 2];
        float d2 = dx * dx + dy * dy + dz * dz;
        s_d2[tid] = d2;
        s_fe[tid * 76 + 64] = to_tf32(d2);
#pragma unroll
        for (int j = 65; j < 72; j++) s_fe[tid * 76 + j] = 0.f;
    }
    __syncthreads();
    for (int idx = tid; idx < 128 * 32; idx += 256) {
        int e = idx >> 5, i = idx & 31;
        float xs = s_d2[e] * __int_as_float((127 - i) << 23);
        float sv, cv;
        __sincosf(xs, &sv, &cv);   // fast path; err ~1e-5 << tf32 rounding below
        s_fe[e * 76 + i] = to_tf32(sv);
        s_fe[e * 76 + 32 + i] = to_tf32(cv);
    }

    int wid = tid >> 5, lane = tid & 31;
    int g = lane >> 2, tig = lane & 3;
    int r0 = wid << 4;

    float acc[4][4];
#pragma unroll
    for (int t = 0; t < 4; t++)
#pragma unroll
        for (int u = 0; u < 4; u++) acc[t][u] = 0.f;

    for (int c = 0; c < 11; c++) {
        int cb = c << 6;
        __syncthreads();
        for (int idx = tid; idx < 72 * 64; idx += 256) {
            int k = idx >> 6, n = idx & 63;
            int gj = cb + n;
            float v = (k < 65 && gj < HID) ? W1[(256 + k) * HID + gj] : 0.f;
            s_W1c[k * 68 + n] = to_tf32(v);
        }
        for (int idx = tid; idx < 64 * 32; idx += 256) {
            int j = idx >> 5, n = idx & 31;
            int gj = cb + j;
            float v = (gj < HID) ? W2[gj * MD + n] : 0.f;
            s_W2c[j * 36 + n] = to_tf32(v);
        }
        for (int it = tid; it < 128 * 16; it += 256) {
            int e = it >> 4, q = it & 15;
            int col = cb + (q << 2);
            float4 r = make_float4(0.f, 0.f, 0.f, 0.f);
            if (col < HID) {
                float4 pa = *(const float4*)&g_Pa[s_dst[e] * PLD + col];
                float4 pb = *(const float4*)&g_Pb[s_src[e] * PLD + col];
                r.x = pa.x + pb.x + b1[col];
                r.y = (col + 1 < HID) ? pa.y + pb.y + b1[col + 1] : 0.f;
                r.z = (col + 2 < HID) ? pa.z + pb.z + b1[col + 2] : 0.f;
                r.w = (col + 3 < HID) ? pa.w + pb.w + b1[col + 3] : 0.f;
            }
            *(float4*)&s_H[e * 68 + (q << 2)] = r;
        }
        __syncthreads();

        float c1[8][4];
#pragma unroll
        for (int t = 0; t < 8; t++)
#pragma unroll
            for (int u = 0; u < 4; u++) c1[t][u] = 0.f;
#pragma unroll
        for (int ks = 0; ks < 9; ks++) {
            int k0 = ks << 3;
            unsigned a0 = __float_as_uint(s_fe[(r0 + g) * 76 + k0 + tig]);
            unsigned a1 = __float_as_uint(s_fe[(r0 + g + 8) * 76 + k0 + tig]);
            unsigned a2 = __float_as_uint(s_fe[(r0 + g) * 76 + k0 + tig + 4]);
            unsigned a3 = __float_as_uint(s_fe[(r0 + g + 8) * 76 + k0 + tig + 4]);
#pragma unroll
            for (int t = 0; t < 8; t++) {
                unsigned b0v = __float_as_uint(s_W1c[(k0 + tig) * 68 + (t << 3) + g]);
                unsigned b1v = __float_as_uint(s_W1c[(k0 + tig + 4) * 68 + (t << 3) + g]);
                mma_tf32(c1[t], a0, a1, a2, a3, b0v, b1v);
            }
        }
#pragma unroll
        for (int t = 0; t < 8; t++) {
            int col = (t << 3) + (tig << 1);
            int i00 = (r0 + g) * 68 + col;
            int i10 = (r0 + g + 8) * 68 + col;
            s_H[i00] = to_tf32(silu_f(c1[t][0] + s_H[i00]));
            s_H[i00 + 1] = to_tf32(silu_f(c1[t][1] + s_H[i00 + 1]));
            s_H[i10] = to_tf32(silu_f(c1[t][2] + s_H[i10]));
            s_H[i10 + 1] = to_tf32(silu_f(c1[t][3] + s_H[i10 + 1]));
        }
        __syncthreads();

#pragma unroll
        for (int ks = 0; ks < 8; ks++) {
            int k0 = ks << 3;
            unsigned a0 = __float_as_uint(s_H[(r0 + g) * 68 + k0 + tig]);
            unsigned a1 = __float_as_uint(s_H[(r0 + g + 8) * 68 + k0 + tig]);
            unsigned a2 = __float_as_uint(s_H[(r0 + g) * 68 + k0 + tig + 4]);
            unsigned a3 = __float_as_uint(s_H[(r0 + g + 8) * 68 + k0 + tig + 4]);
#pragma unroll
            for (int t = 0; t < 4; t++) {
                unsigned b0v = __float_as_uint(s_W2c[(k0 + tig) * 36 + (t << 3) + g]);
                unsigned b1v = __float_as_uint(s_W2c[(k0 + tig + 4) * 36 + (t << 3) + g]);
                mma_tf32(acc[t], a0, a1, a2, a3, b0v, b1v);
            }
        }
    }

    float vlo[8], vhi[8];
    float Slo = 0.f, Shi = 0.f;
#pragma unroll
    for (int t = 0; t < 4; t++) {
        int col = (t << 3) + (tig << 1);
        float v0 = silu_f(acc[t][0] + b2[col]);
        float v1 = silu_f(acc[t][1] + b2[col + 1]);
        float v2 = silu_f(acc[t][2] + b2[col]);
        float v3 = silu_f(acc[t][3] + b2[col + 1]);
        vlo[t * 2] = v0; vlo[t * 2 + 1] = v1;
        vhi[t * 2] = v2; vhi[t * 2 + 1] = v3;
        Slo += v0 + v1; Shi += v2 + v3;
    }
    Slo += __shfl_xor_sync(0xffffffffu, Slo, 1);
    Slo += __shfl_xor_sync(0xffffffffu, Slo, 2);
    Shi += __shfl_xor_sync(0xffffffffu, Shi, 1);
    Shi += __shfl_xor_sync(0xffffffffu, Shi, 2);
    float mlo = Slo * (1.f / 32.f), mhi = Shi * (1.f / 32.f);
    float Vlo = 0.f, Vhi = 0.f;
#pragma unroll
    for (int u = 0; u < 8; u++) {
        float d0 = vlo[u] - mlo; Vlo += d0 * d0;
        float d1 = vhi[u] - mhi; Vhi += d1 * d1;
    }
    Vlo += __shfl_xor_sync(0xffffffffu, Vlo, 1);
    Vlo += __shfl_xor_sync(0xffffffffu, Vlo, 2);
    Vhi += __shfl_xor_sync(0xffffffffu, Vhi, 1);
    Vhi += __shfl_xor_sync(0xffffffffu, Vhi, 2);
    float ilo = rsqrtf(Vlo * (1.f / 32.f) + EPSF);
    float ihi = rsqrtf(Vhi * (1.f / 32.f) + EPSF);
    int dlo = s_dst[r0 + g], dhi = s_dst[r0 + g + 8];
#pragma unroll
    for (int t = 0; t < 4; t++) {
#pragma unroll
        for (int d = 0; d < 2; d++) {
            int col = (t << 3) + (tig << 1) + d;
            atomicAdd(&g_seg[dlo * MD + col], (vlo[t * 2 + d] - mlo) * ilo * eng[col] + enb[col]);
            atomicAdd(&g_seg[dhi * MD + col], (vhi[t * 2 + d] - mhi) * ihi * eng[col] + enb[col]);
        }
    }
}

// ---------------- node pre ----------------
__global__ void k_node_pre(int off, const float* __restrict__ eng, const float* __restrict__ enb,
                           const float* __restrict__ n1g, const float* __restrict__ n1b) {
    int node = blockIdx.x * 8 + (threadIdx.x >> 5);
    int lane = threadIdx.x & 31;
    if (node >= NN) return;

    float x = g_seg[node * MD + lane] / fmaxf(g_cnt[node], 1.f);
    float S = x;
#pragma unroll
    for (int o = 16; o; o >>= 1) S += __shfl_xor_sync(0xffffffffu, S, o);
    float mean = S * (1.f / 32.f);
    float d = x - mean;
    float V = d * d;
#pragma unroll
    for (int o = 16; o; o >>= 1) V += __shfl_xor_sync(0xffffffffu, V, o);
    V *= (1.f / 32.f);
    g_z[node * 160 + 128 + lane] = d * rsqrtf(V + EPSF) * eng[lane] + enb[lane];

    float4 v = *(const float4*)&g_cat[node * CAT + off + lane * 4];
    S = v.x + v.y + v.z + v.w;
#pragma unroll
    for (int o = 16; o; o >>= 1) S += __shfl_xor_sync(0xffffffffu, S, o);
    mean = S * (1.f / 128.f);
    float dx = v.x - mean, dy = v.y - mean, dz = v.z - mean, dw = v.w - mean;
    V = dx * dx + dy * dy + dz * dz + dw * dw;
#pragma unroll
    for (int o = 16; o; o >>= 1) V += __shfl_xor_sync(0xffffffffu, V, o);
    V *= (1.f / 128.f);
    float inv = rsqrtf(V + EPSF);
    float4 g4 = *(const float4*)&n1g[lane * 4];
    float4 b4 = *(const float4*)&n1b[lane * 4];
    float4 o4;
    o4.x = dx * inv * g4.x + b4.x;
    o4.y = dy * inv * g4.y + b4.y;
    o4.z = dz * inv * g4.z + b4.z;
    o4.w = dw * inv * g4.w + b4.w;
    *(float4*)&g_z[node * 160 + lane * 4] = o4;
}

// ---------------- node post ----------------
__global__ void k_node_post(int off, const float* __restrict__ n2g, const float* __restrict__ n2b) {
    int node = blockIdx.x * 8 + (threadIdx.x >> 5);
    int lane = threadIdx.x & 31;
    if (node >= NN) return;
    float4 v = *(const float4*)&g_h2[node * 128 + lane * 4];
    float S = v.x + v.y + v.z + v.w;
#pragma unroll
    for (int o = 16; o; o >>= 1) S += __shfl_xor_sync(0xffffffffu, S, o);
    float mean = S * (1.f / 128.f);
    float dx = v.x - mean, dy = v.y - mean, dz = v.z - mean, dw = v.w - mean;
    float V = dx * dx + dy * dy + dz * dz + dw * dw;
#pragma unroll
    for (int o = 16; o; o >>= 1) V += __shfl_xor_sync(0xffffffffu, V, o);
    V *= (1.f / 128.f);
    float inv = rsqrtf(V + EPSF);
    float4 g4 = *(const float4*)&n2g[lane * 4];
    float4 b4 = *(const float4*)&n2b[lane * 4];
    float4 old = *(const float4*)&g_cat[node * CAT + off + lane * 4];
    float4 o4;
    o4.x = old.x + dx * inv * g4.x + b4.x;
    o4.y = old.y + dy * inv * g4.y + b4.y;
    o4.z = old.z + dz * inv * g4.z + b4.z;
    o4.w = old.w + dw * inv * g4.w + b4.w;
    *(float4*)&g_cat[node * CAT + off + 128 + lane * 4] = o4;
}

// ---------------- graph head ----------------
__global__ void k_graph(const float* __restrict__ g1W, const float* __restrict__ g1b,
                        const float* __restrict__ g2W, const float* __restrict__ g2b,
                        const float* __restrict__ g3W, const float* __restrict__ g3b,
                        float* __restrict__ out) {
    __shared__ float h[256], t[256];
    int g = blockIdx.x, tid = threadIdx.x;
    float c = fmaxf(g_pcnt[g], 1.f);
    h[tid] = g_pool[g * 256 + tid] / c;
    __syncthreads();
    float a = g1b[tid];
    for (int k = 0; k < 256; k++) a += h[k] * g1W[k * 256 + tid];
    t[tid] = silu_f(a);
    __syncthreads();
    h[tid] = t[tid];
    __syncthreads();
    a = g2b[tid];
    for (int k = 0; k < 256; k++) a += h[k] * g2W[k * 256 + tid];
    t[tid] = silu_f(a);
    __syncthreads();
    h[tid] = t[tid];
    __syncthreads();
    t[tid] = h[tid] * g3W[tid];
    __syncthreads();
    for (int s = 128; s; s >>= 1) {
        if (tid < s) t[tid] += t[tid + s];
        __syncthreads();
    }
    if (tid == 0) out[g] = t[0] + g3b[0];
}

// ---------------- launch ----------------
extern "C" void kernel_launch(void* const* d_in, const int* in_sizes, int n_in,
                              void* d_out, int out_size) {
    const int* atomids = (const int*)d_in[0];
    const float* coords = (const float*)d_in[1];
    const int* eidx = (const int*)d_in[2];
    const int* batch = (const int*)d_in[3];
    const float* emb_w = (const float*)d_in[4];
    const float* eW1 = (const float*)d_in[5];
    const float* eb1 = (const float*)d_in[6];
    const float* eW2 = (const float*)d_in[7];
    const float* eb2 = (const float*)d_in[8];
    const float* en_g = (const float*)d_in[9];
    const float* en_b = (const float*)d_in[10];
    const float* nn1_g = (const float*)d_in[11];
    const float* nn1_b = (const float*)d_in[12];
    const float* nW1 = (const float*)d_in[13];
    const float* nb1 = (const float*)d_in[14];
    const float* nW2 = (const float*)d_in[15];
    const float* nb2 = (const float*)d_in[16];
    const float* nn2_g = (const float*)d_in[17];
    const float* nn2_b = (const float*)d_in[18];
    const float* f1W = (const float*)d_in[19];
    const float* f1b = (const float*)d_in[20];
    const float* f2W = (const float*)d_in[21];
    const float* f2b = (const float*)d_in[22];
    const float* f3W = (const float*)d_in[23];
    const float* f3b = (const float*)d_in[24];
    const float* g1W = (const float*)d_in[25];
    const float* g1b = (const float*)d_in[26];
    const float* g2W = (const float*)d_in[27];
    const float* g2b = (const float*)d_in[28];
    const float* g3W = (const float*)d_in[29];
    const float* g3b = (const float*)d_in[30];
    float* out = (float*)d_out;

    const int smem_edge = (128 * 76 + 128 * 68 + 72 * 68 + 64 * 36 + 128 + 256) * 4;  // 104064 B
    cudaFuncSetAttribute(k_edge2, cudaFuncAttributeMaxDynamicSharedMemorySize, smem_edge);

    float *pcat, *phcat, *pPa, *pPb, *pz, *ph1, *ph2, *pf1, *pf2, *pf3;
    cudaGetSymbolAddress((void**)&pcat, g_cat);
    cudaGetSymbolAddress((void**)&phcat, g_hcat);
    cudaGetSymbolAddress((void**)&pPa, g_Pa);
    cudaGetSymbolAddress((void**)&pPb, g_Pb);
    cudaGetSymbolAddress((void**)&pz, g_z);
    cudaGetSymbolAddress((void**)&ph1, g_h1);
    cudaGetSymbolAddress((void**)&ph2, g_h2);
    cudaGetSymbolAddress((void**)&pf1, g_f1);
    cudaGetSymbolAddress((void**)&pf2, g_f2);
    cudaGetSymbolAddress((void**)&pf3, g_f3);

    k_zero_start<<<64, 256>>>();
    k_deg<<<(NE + 255) / 256, 256>>>(eidx);
    k_embed<<<(NN * EMB + 255) / 256, 256>>>(atomids, emb_w);

    const int MB = (NN + 127) / 128;  // 79

    for (int k = 0; k < 5; k++) {
        int off = 128 * k;
        k_gemm3t<<<dim3(11, MB), 256>>>(pcat + off, eW1 + (size_t)k * EIN * HID, nullptr, pPa,
                                        NN, HID, EMB, CAT, HID, PLD, 0);
        k_gemm3t<<<dim3(11, MB), 256>>>(pcat + off, eW1 + (size_t)k * EIN * HID + (size_t)EMB * HID,
                                        nullptr, pPb, NN, HID, EMB, CAT, HID, PLD, 0);
        k_zero_seg<<<(NN * MD + 255) / 256, 256>>>();
        k_edge2<<<NE / 128, 256, smem_edge>>>(eidx, coords,
                                              eW1 + (size_t)k * EIN * HID, eb1 + k * HID,
                                              eW2 + (size_t)k * HID * MD, eb2 + k * MD,
                                              en_g + k * MD, en_b + k * MD);
        k_node_pre<<<NN / 8, 256>>>(off, en_g + k * MD, en_b + k * MD,
                                    nn1_g + k * EMB, nn1_b + k * EMB);
        k_gemm3t<<<dim3(4, MB), 256>>>(pz, nW1 + (size_t)k * 160 * 256, nb1 + k * 256, ph1,
                                       NN, 256, 160, 160, 256, 256, 1);
        k_gemm3t<<<dim3(2, MB), 256>>>(ph1, nW2 + (size_t)k * 256 * 128, nb2 + k * 128, ph2,
                                       NN, 128, 256, 256, 128, 128, 0);
        k_node_post<<<NN / 8, 256>>>(off, nn2_g + k * EMB, nn2_b + k * EMB);
    }

    k_silucat<<<(NN * CAT + 255) / 256, 256>>>();
    k_gemm3t<<<dim3(4, MB), 256>>>(phcat, f1W, f1b, pf1, NN, 256, CAT, CAT, 256, 256, 1);
    k_gemm3t<<<dim3(4, MB), 256>>>(pf1, f2W, f2b, pf2, NN, 256, 256, 256, 256, 256, 1);
    k_gemm3t<<<dim3(4, MB), 256>>>(pf2, f3W, f3b, pf3, NN, 256, 256, 256, 256, 256, 1);
    k_pool<<<(NN * 256 + 255) / 256, 256>>>(batch);
    k_graph<<<NG, 256>>>(g1W, g1b, g2W, g2b, g3W, g3b, out);
}